// round 4
// baseline (speedup 1.0000x reference)
#include <cuda_runtime.h>
#include <math.h>

#define B_SZ    8
#define T_LEN   4096
#define D_INP   128
#define D_OUTP  128
#define N_ST    256
#define CHUNKS  128                  /* 32-step scan chunks */
#define TT      64                   /* time-tile per block (2 chunks) */
#define NBLK    (B_SZ * T_LEN / TT)  /* 512 */
#define N_ROWS  320                  /* 256 state rows + 64 x-pair rows */

typedef unsigned long long u64;

// ---------------- scratch ----------------
__device__ u64    g_Bsw [128 * 32 * 10];        // [k][ng][10]: pk2(gB_re,gB_im) n=ng*8+r
__device__ u64    g_CDsw[N_ROWS * 16 * 10];     // [R][dg][10]: C rows / folded-D rows
__device__ float2 g_lam [N_ST];
__device__ float2 g_lamL[N_ST];                 // lambda^32
__device__ float2 g_states[(size_t)B_SZ * T_LEN * N_ST];
__device__ float2 g_carry[B_SZ * CHUNKS * N_ST];
__device__ float2 g_pref [B_SZ * CHUNKS * N_ST];

// ---------------- helpers ----------------
__device__ __forceinline__ u64 pk2(float lo, float hi) {
    u64 r; asm("mov.b64 %0, {%1, %2};" : "=l"(r) : "f"(lo), "f"(hi)); return r;
}
__device__ __forceinline__ void upk2(u64 v, float& lo, float& hi) {
    asm("mov.b64 {%0, %1}, %2;" : "=f"(lo), "=f"(hi) : "l"(v));
}
__device__ __forceinline__ u64 fma2(u64 a, u64 b, u64 c) {
    u64 d; asm("fma.rn.f32x2 %0, %1, %2, %3;" : "=l"(d) : "l"(a), "l"(b), "l"(c)); return d;
}
__device__ __forceinline__ float2 cmul(float2 a, float2 b) {
    return make_float2(a.x * b.x - a.y * b.y, a.x * b.y + a.y * b.x);
}

// ---------------- kernel 0: parameter prep (swizzled layouts) ----------------
__global__ void lru_prep(const float* __restrict__ nu_log,
                         const float* __restrict__ theta_log,
                         const float* __restrict__ gamma_log,
                         const float* __restrict__ B_re, const float* __restrict__ B_im,
                         const float* __restrict__ C_re, const float* __restrict__ C_im,
                         const float* __restrict__ Dm) {
    int idx = blockIdx.x * blockDim.x + threadIdx.x;   // grid covers 51200
    if (idx < N_ST) {
        float la = expf(-expf(nu_log[idx]));
        float ph = expf(theta_log[idx]);
        float2 lam = make_float2(la * cosf(ph), la * sinf(ph));
        g_lam[idx] = lam;
        float2 p = lam;
        #pragma unroll
        for (int i = 0; i < 5; i++) p = cmul(p, p);     // lam^32
        g_lamL[idx] = p;
    }
    if (idx < 128 * 32 * 10) {         // g_Bsw
        int r  = idx % 10;
        int ng = (idx / 10) % 32;
        int k  = idx / 320;
        u64 v = 0ULL;
        if (r < 8) {
            int n = ng * 8 + r;
            float g = expf(gamma_log[n]);
            v = pk2(g * B_re[n * D_INP + k], g * B_im[n * D_INP + k]);
        }
        g_Bsw[idx] = v;
    }
    if (idx < N_ROWS * 16 * 10) {      // g_CDsw
        int r  = idx % 10;
        int dg = (idx / 10) % 16;
        int R  = idx / 160;
        u64 v = 0ULL;
        if (r < 8) {
            int d = dg * 8 + r;
            if (R < N_ST) {
                v = pk2(C_re[d * N_ST + R], C_im[d * N_ST + R]);
            } else {
                int kp = R - N_ST;
                v = pk2(Dm[d * D_INP + 2 * kp], -Dm[d * D_INP + 2 * kp + 1]);
            }
        }
        g_CDsw[idx] = v;
    }
}

// ---------------- kernel 1: Bu = x @ BcT + chunk-local scan ----------------
// smem: bsw u64[16*32*10] = 40960B | xs float[128][68] = 34816B
#define K1_SMEM (16 * 32 * 10 * 8 + 128 * 68 * 4)

__global__ __launch_bounds__(256, 1) void lru_bu_scan(const float* __restrict__ x) {
    extern __shared__ char smem[];
    u64*   bsw = (u64*)smem;
    float* xs  = (float*)(smem + 16 * 32 * 10 * 8);

    int b   = blockIdx.x >> 6;           // /64
    int c2  = blockIdx.x & 63;
    int tid = threadIdx.x;
    int lane = tid & 31, w = tid >> 5;
    int ngl = lane & 3, tg = lane >> 2;  // tg 0..7
    int ng  = w * 4 + ngl;               // 0..31
    size_t tbase = (size_t)b * T_LEN + c2 * TT;

    // ---- stage x transposed: xs[k][t], stride 68 floats ----
    {
        int k = tid & 127, half = tid >> 7;
        const float* xp = x + tbase * D_INP + k;
        #pragma unroll
        for (int q = 0; q < 8; q++) {
            int t0 = half * 32 + q * 4;
            float4 v;
            v.x = xp[(t0 + 0) * D_INP];
            v.y = xp[(t0 + 1) * D_INP];
            v.z = xp[(t0 + 2) * D_INP];
            v.w = xp[(t0 + 3) * D_INP];
            *(float4*)(xs + k * 68 + t0) = v;
        }
    }

    u64 acc[64];
    #pragma unroll
    for (int i = 0; i < 64; i++) acc[i] = 0ULL;

    for (int kt = 0; kt < 8; kt++) {
        __syncthreads();
        const float4* src = (const float4*)(g_Bsw + kt * 5120);
        float4* dst = (float4*)bsw;
        #pragma unroll
        for (int i = 0; i < 10; i++) dst[tid + i * 256] = src[tid + i * 256];
        __syncthreads();
        #pragma unroll 4
        for (int kk = 0; kk < 16; kk++) {
            const ulonglong2* bp = (const ulonglong2*)(bsw + (kk * 32 + ng) * 10);
            ulonglong2 b01 = bp[0], b23 = bp[1], b45 = bp[2], b67 = bp[3];
            int k = kt * 16 + kk;
            float4 xa = *(const float4*)(xs + k * 68 + tg * 8);
            float4 xb = *(const float4*)(xs + k * 68 + tg * 8 + 4);
            u64 xd[8];
            xd[0] = pk2(xa.x, xa.x); xd[1] = pk2(xa.y, xa.y);
            xd[2] = pk2(xa.z, xa.z); xd[3] = pk2(xa.w, xa.w);
            xd[4] = pk2(xb.x, xb.x); xd[5] = pk2(xb.y, xb.y);
            xd[6] = pk2(xb.z, xb.z); xd[7] = pk2(xb.w, xb.w);
            u64 bv[8] = {b01.x, b01.y, b23.x, b23.y, b45.x, b45.y, b67.x, b67.y};
            #pragma unroll
            for (int i = 0; i < 8; i++)
                #pragma unroll
                for (int j = 0; j < 8; j++)
                    acc[i * 8 + j] = fma2(xd[j], bv[i], acc[i * 8 + j]);
        }
    }

    // ---- chunk-local scan via warp shuffles (segments of 8 over tg) ----
    int tgm = tg & 3;                 // position within 32-chunk
    int cc  = tg >> 2;                // which chunk of the two
    int cblk = b * CHUNKS + c2 * 2 + cc;

    #pragma unroll
    for (int i = 0; i < 8; i++) {
        int n = ng * 8 + i;
        float2 lam = g_lam[n];
        float2 l2 = cmul(lam, lam), l4 = cmul(l2, l2);
        float2 l8 = cmul(l4, l4),  l16 = cmul(l8, l8);

        float sr[8], si[8];
        float cr = 0.f, ci = 0.f;
        #pragma unroll
        for (int j = 0; j < 8; j++) {
            float br, bi; upk2(acc[i * 8 + j], br, bi);
            float nr = fmaf(lam.x, cr, fmaf(-lam.y, ci, br));
            float ni = fmaf(lam.x, ci, fmaf( lam.y, cr, bi));
            cr = nr; ci = ni; sr[j] = nr; si[j] = ni;
        }
        // Kogge-Stone over segment ends within each 4-tg chunk group
        float vr = sr[7], vi = si[7];
        float tr = __shfl_up_sync(0xffffffffu, vr, 4);
        float ti = __shfl_up_sync(0xffffffffu, vi, 4);
        if (tgm >= 1) {
            vr = fmaf(l8.x, tr, fmaf(-l8.y, ti, vr));
            vi = fmaf(l8.x, ti, fmaf( l8.y, tr, vi));
        }
        tr = __shfl_up_sync(0xffffffffu, vr, 8);
        ti = __shfl_up_sync(0xffffffffu, vi, 8);
        if (tgm >= 2) {
            vr = fmaf(l16.x, tr, fmaf(-l16.y, ti, vr));
            vi = fmaf(l16.x, ti, fmaf( l16.y, tr, vi));
        }
        float Cr = __shfl_up_sync(0xffffffffu, vr, 4);
        float Ci = __shfl_up_sync(0xffffffffu, vi, 4);
        if (tgm == 0) { Cr = 0.f; Ci = 0.f; }

        float pwr = lam.x, pwi = lam.y;
        float2* sp = g_states + (tbase + tg * 8) * N_ST + n;
        #pragma unroll
        for (int j = 0; j < 8; j++) {
            float rr = fmaf(pwr, Cr, fmaf(-pwi, Ci, sr[j]));
            float ri = fmaf(pwr, Ci, fmaf( pwi, Cr, si[j]));
            sp[j * N_ST] = make_float2(rr, ri);
            if (j == 7 && tgm == 3) g_carry[cblk * N_ST + n] = make_float2(rr, ri);
            float npr = fmaf(pwr, lam.x, -pwi * lam.y);
            float npi = fmaf(pwr, lam.y,  pwi * lam.x);
            pwr = npr; pwi = npi;
        }
    }
}

// ---------------- kernel 1b: exclusive prefix over chunk carries (MLP-batched) ----------------
__global__ void lru_prefix() {
    int b = blockIdx.x;            // 8
    int n = threadIdx.x;           // 256
    float2 lamL = g_lamL[n];
    float2 pre = make_float2(0.f, 0.f);
    const float2* cp = g_carry + b * CHUNKS * N_ST + n;
    float2*       pp = g_pref  + b * CHUNKS * N_ST + n;
    #pragma unroll 1
    for (int cb = 0; cb < CHUNKS; cb += 16) {
        float2 cj[16];
        #pragma unroll
        for (int u = 0; u < 16; u++) cj[u] = cp[(cb + u) * N_ST];
        #pragma unroll
        for (int u = 0; u < 16; u++) {
            pp[(cb + u) * N_ST] = pre;
            pre = cmul(lamL, pre);
            pre.x += cj[u].x; pre.y += cj[u].y;
        }
    }
}

// ---------------- kernel 2: correction + y = Re(states @ C^T) + x @ D^T ----------------
// smem: stT u64[128][66] = 67584B | ct u64[32*16*10] = 40960B  -> 108544B
#define K2_SMEM (128 * 66 * 8 + 32 * 16 * 10 * 8)

__global__ __launch_bounds__(128, 2) void lru_fix_out(const float* __restrict__ x,
                                                      float* __restrict__ y) {
    extern __shared__ char smem[];
    u64* stT = (u64*)smem;
    u64* ct  = (u64*)(smem + 128 * 66 * 8);

    int b   = blockIdx.x >> 6;
    int c2  = blockIdx.x & 63;
    int tid = threadIdx.x;
    int lane = tid & 31, w = tid >> 5;
    int dgl = lane & 3, tg = lane >> 2;  // tg 0..7
    int dg  = w * 4 + dgl;               // 0..15
    size_t tbase = (size_t)b * T_LEN + c2 * TT;

    u64 acc[64];
    #pragma unroll
    for (int i = 0; i < 64; i++) acc[i] = 0ULL;

    for (int p = 0; p < 3; p++) {
        int rows = (p == 2) ? 64 : 128;
        __syncthreads();                      // stT reuse barrier
        // ---- phase A: build stT rows ----
        if (tid < rows) {
            int R = p * 128 + tid;
            if (R < N_ST) {
                int n = R;
                float2 lam = g_lam[n];
                #pragma unroll
                for (int cc = 0; cc < 2; cc++) {
                    float2 pre = g_pref[(b * CHUNKS + c2 * 2 + cc) * N_ST + n];
                    float pwr = lam.x, pwi = lam.y;
                    const float2* sp = g_states + (tbase + cc * 32) * N_ST + n;
                    #pragma unroll 8
                    for (int t = 0; t < 32; t++) {
                        float2 lv = sp[t * N_ST];
                        float rr = fmaf(pwr, pre.x, fmaf(-pwi, pre.y, lv.x));
                        float ri = fmaf(pwr, pre.y, fmaf( pwi, pre.x, lv.y));
                        stT[tid * 66 + cc * 32 + t] = pk2(rr, ri);
                        float npr = fmaf(pwr, lam.x, -pwi * lam.y);
                        float npi = fmaf(pwr, lam.y,  pwi * lam.x);
                        pwr = npr; pwi = npi;
                    }
                }
            } else {
                int kp = R - N_ST;
                const float* xp = x + tbase * D_INP + 2 * kp;
                #pragma unroll 8
                for (int t = 0; t < TT; t++)
                    stT[tid * 66 + t] = *(const u64*)(xp + (size_t)t * D_INP);
            }
        }
        // ---- phase B ----
        int ntiles = rows >> 5;
        for (int nt = 0; nt < ntiles; nt++) {
            __syncthreads();
            const float4* src = (const float4*)(g_CDsw + (p * 128 + nt * 32) * 160);
            float4* dst = (float4*)ct;
            #pragma unroll
            for (int i = 0; i < 20; i++) dst[tid + i * 128] = src[tid + i * 128];
            __syncthreads();
            #pragma unroll 4
            for (int kk = 0; kk < 32; kk++) {
                const ulonglong2* cp2 = (const ulonglong2*)(ct + (kk * 16 + dg) * 10);
                ulonglong2 c01 = cp2[0], c23 = cp2[1], c45 = cp2[2], c67 = cp2[3];
                const ulonglong2* sp2 = (const ulonglong2*)(stT + (nt * 32 + kk) * 66 + tg * 8);
                ulonglong2 s01 = sp2[0], s23 = sp2[1], s45 = sp2[2], s67 = sp2[3];
                u64 cv[8] = {c01.x, c01.y, c23.x, c23.y, c45.x, c45.y, c67.x, c67.y};
                u64 sv[8] = {s01.x, s01.y, s23.x, s23.y, s45.x, s45.y, s67.x, s67.y};
                #pragma unroll
                for (int i = 0; i < 8; i++)
                    #pragma unroll
                    for (int j = 0; j < 8; j++)
                        acc[i * 8 + j] = fma2(sv[j], cv[i], acc[i * 8 + j]);
            }
        }
    }

    // ---- epilogue: Re() = lo - hi (D-term folded via sign trick) ----
    float* yp = y + (tbase + tg * 8) * D_OUTP + dg * 8;
    #pragma unroll
    for (int j = 0; j < 8; j++) {
        float r[8];
        #pragma unroll
        for (int i = 0; i < 8; i++) {
            float a, bb; upk2(acc[i * 8 + j], a, bb);
            r[i] = a - bb;
        }
        *(float4*)(yp + (size_t)j * D_OUTP)     = make_float4(r[0], r[1], r[2], r[3]);
        *(float4*)(yp + (size_t)j * D_OUTP + 4) = make_float4(r[4], r[5], r[6], r[7]);
    }
}

// ---------------- launch ----------------
extern "C" void kernel_launch(void* const* d_in, const int* in_sizes, int n_in,
                              void* d_out, int out_size) {
    (void)in_sizes; (void)n_in; (void)out_size;
    const float* x         = (const float*)d_in[0];
    const float* nu_log    = (const float*)d_in[1];
    const float* theta_log = (const float*)d_in[2];
    const float* gamma_log = (const float*)d_in[3];
    const float* B_re      = (const float*)d_in[4];
    const float* B_im      = (const float*)d_in[5];
    const float* C_re      = (const float*)d_in[6];
    const float* C_im      = (const float*)d_in[7];
    const float* Dm        = (const float*)d_in[8];
    float* y = (float*)d_out;

    cudaFuncSetAttribute(lru_bu_scan, cudaFuncAttributeMaxDynamicSharedMemorySize, K1_SMEM);
    cudaFuncSetAttribute(lru_fix_out, cudaFuncAttributeMaxDynamicSharedMemorySize, K2_SMEM);

    lru_prep<<<200, 256>>>(nu_log, theta_log, gamma_log, B_re, B_im, C_re, C_im, Dm);
    lru_bu_scan<<<NBLK, 256, K1_SMEM>>>(x);
    lru_prefix<<<B_SZ, N_ST>>>();
    lru_fix_out<<<NBLK, 128, K2_SMEM>>>(x, y);
}

// round 5
// speedup vs baseline: 1.0348x; 1.0348x over previous
#include <cuda_runtime.h>
#include <math.h>

#define B_SZ    8
#define T_LEN   4096
#define D_INP   128
#define D_OUTP  128
#define N_ST    256
#define CHUNKS  128                  /* 32-step scan chunks */
#define TT      64                   /* k1 time-tile */
#define NBLK1   (B_SZ * T_LEN / TT)  /* 512 */
#define TT2     128                  /* k2 time-tile */
#define NBLK2   (B_SZ * T_LEN / TT2) /* 256 */
#define N_ROWS  320                  /* 256 state rows + 64 x-pair rows */

typedef unsigned long long u64;

// q-permutation: g_states column q holds channel n(q)
__host__ __device__ __forceinline__ int qperm(int q) {
    return (q & ~31) | ((q & 3) << 3) | ((q >> 2) & 7);
}

// ---------------- scratch ----------------
__device__ u64    g_Bsw [128 * 32 * 10];        // [k][ng][10]: pk2(gB_re,gB_im), n=ng*8+r
__device__ u64    g_CDsw[N_ROWS * 16 * 10];     // [q][dg][10]: C rows (q-permuted) / folded-D rows
__device__ float2 g_lam [N_ST];
__device__ float2 g_lamL[N_ST];                 // lambda^32
__device__ float2 g_states[(size_t)B_SZ * T_LEN * N_ST];   // [t][q]
__device__ float2 g_carry[B_SZ * CHUNKS * N_ST];
__device__ float2 g_pref [B_SZ * CHUNKS * N_ST];

// ---------------- helpers ----------------
__device__ __forceinline__ u64 pk2(float lo, float hi) {
    u64 r; asm("mov.b64 %0, {%1, %2};" : "=l"(r) : "f"(lo), "f"(hi)); return r;
}
__device__ __forceinline__ void upk2(u64 v, float& lo, float& hi) {
    asm("mov.b64 {%0, %1}, %2;" : "=f"(lo), "=f"(hi) : "l"(v));
}
__device__ __forceinline__ u64 fma2(u64 a, u64 b, u64 c) {
    u64 d; asm("fma.rn.f32x2 %0, %1, %2, %3;" : "=l"(d) : "l"(a), "l"(b), "l"(c)); return d;
}
__device__ __forceinline__ float2 cmul(float2 a, float2 b) {
    return make_float2(a.x * b.x - a.y * b.y, a.x * b.y + a.y * b.x);
}

// ---------------- kernel 0: parameter prep ----------------
__global__ void lru_prep(const float* __restrict__ nu_log,
                         const float* __restrict__ theta_log,
                         const float* __restrict__ gamma_log,
                         const float* __restrict__ B_re, const float* __restrict__ B_im,
                         const float* __restrict__ C_re, const float* __restrict__ C_im,
                         const float* __restrict__ Dm) {
    int idx = blockIdx.x * blockDim.x + threadIdx.x;   // grid covers 51200
    if (idx < N_ST) {
        float la = expf(-expf(nu_log[idx]));
        float ph = expf(theta_log[idx]);
        float2 lam = make_float2(la * cosf(ph), la * sinf(ph));
        g_lam[idx] = lam;
        float2 p = lam;
        #pragma unroll
        for (int i = 0; i < 5; i++) p = cmul(p, p);     // lam^32
        g_lamL[idx] = p;
    }
    if (idx < 128 * 32 * 10) {         // g_Bsw
        int r  = idx % 10;
        int ng = (idx / 10) % 32;
        int k  = idx / 320;
        u64 v = 0ULL;
        if (r < 8) {
            int n = ng * 8 + r;
            float g = expf(gamma_log[n]);
            v = pk2(g * B_re[n * D_INP + k], g * B_im[n * D_INP + k]);
        }
        g_Bsw[idx] = v;
    }
    if (idx < N_ROWS * 16 * 10) {      // g_CDsw (q-permuted state rows + folded D)
        int r  = idx % 10;
        int dg = (idx / 10) % 16;
        int R  = idx / 160;
        u64 v = 0ULL;
        if (r < 8) {
            int d = dg * 8 + r;
            if (R < N_ST) {
                int n = qperm(R);
                v = pk2(C_re[d * N_ST + n], C_im[d * N_ST + n]);
            } else {
                int kp = R - N_ST;
                v = pk2(Dm[d * D_INP + 2 * kp], -Dm[d * D_INP + 2 * kp + 1]);
            }
        }
        g_CDsw[idx] = v;
    }
}

// ---------------- kernel 1: Bu = x @ BcT + chunk-local scan ----------------
// smem: bsw u64[16*32*10] = 40960B | xs u64[128][66] = 67584B
#define K1_SMEM (16 * 32 * 10 * 8 + 128 * 66 * 8)

__global__ __launch_bounds__(256, 1) void lru_bu_scan(const float* __restrict__ x) {
    extern __shared__ char smem[];
    u64* bsw = (u64*)smem;
    u64* xs  = (u64*)(smem + 16 * 32 * 10 * 8);    // [k][sigma(t)] duplicated pairs

    int b   = blockIdx.x >> 6;
    int c2  = blockIdx.x & 63;
    int tid = threadIdx.x;
    int lane = tid & 31, w = tid >> 5;
    int ngl = lane & 3, tg = lane >> 2;  // tg 0..7
    int ng  = w * 4 + ngl;               // 0..31
    size_t tbase = (size_t)b * T_LEN + c2 * TT;

    // ---- stage x: xs[k][sigma(t)] = (v,v), sigma(t) = (t>>3) | ((t&7)<<3) ----
    {
        int k = tid & 127, half = tid >> 7;
        const float* xp = x + tbase * D_INP + k;
        #pragma unroll
        for (int q = 0; q < 8; q++) {
            int t0 = half * 32 + q * 4;
            #pragma unroll
            for (int j = 0; j < 4; j++) {
                int t = t0 + j;
                float v = xp[(size_t)t * D_INP];
                xs[k * 66 + ((t >> 3) | ((t & 7) << 3))] = pk2(v, v);
            }
        }
    }

    u64 acc[64];
    #pragma unroll
    for (int i = 0; i < 64; i++) acc[i] = 0ULL;

    for (int kt = 0; kt < 8; kt++) {
        __syncthreads();
        const float4* src = (const float4*)(g_Bsw + kt * 5120);
        float4* dst = (float4*)bsw;
        #pragma unroll
        for (int i = 0; i < 10; i++) dst[tid + i * 256] = src[tid + i * 256];
        __syncthreads();
        #pragma unroll 4
        for (int kk = 0; kk < 16; kk++) {
            const ulonglong2* bp = (const ulonglong2*)(bsw + (kk * 32 + ng) * 10);
            ulonglong2 b01 = bp[0], b23 = bp[1], b45 = bp[2], b67 = bp[3];
            const u64* xr = xs + (kt * 16 + kk) * 66 + tg;
            u64 xd[8];
            #pragma unroll
            for (int j = 0; j < 8; j++) xd[j] = xr[j * 8];
            u64 bv[8] = {b01.x, b01.y, b23.x, b23.y, b45.x, b45.y, b67.x, b67.y};
            #pragma unroll
            for (int i = 0; i < 8; i++)
                #pragma unroll
                for (int j = 0; j < 8; j++)
                    acc[i * 8 + j] = fma2(xd[j], bv[i], acc[i * 8 + j]);
        }
    }

    // ---- chunk-local scan via warp shuffles ----
    int tgm = tg & 3;                 // position within 32-chunk
    int cc  = tg >> 2;                // which chunk of the two
    int cblk = b * CHUNKS + c2 * 2 + cc;

    #pragma unroll
    for (int i = 0; i < 8; i++) {
        int n = ng * 8 + i;
        float2 lam = g_lam[n];
        float2 l2 = cmul(lam, lam), l4 = cmul(l2, l2);
        float2 l8 = cmul(l4, l4),  l16 = cmul(l8, l8);

        float sr[8], si[8];
        float cr = 0.f, ci = 0.f;
        #pragma unroll
        for (int j = 0; j < 8; j++) {
            float br, bi; upk2(acc[i * 8 + j], br, bi);
            float nr = fmaf(lam.x, cr, fmaf(-lam.y, ci, br));
            float ni = fmaf(lam.x, ci, fmaf( lam.y, cr, bi));
            cr = nr; ci = ni; sr[j] = nr; si[j] = ni;
        }
        float vr = sr[7], vi = si[7];
        float tr = __shfl_up_sync(0xffffffffu, vr, 4);
        float ti = __shfl_up_sync(0xffffffffu, vi, 4);
        if (tgm >= 1) {
            vr = fmaf(l8.x, tr, fmaf(-l8.y, ti, vr));
            vi = fmaf(l8.x, ti, fmaf( l8.y, tr, vi));
        }
        tr = __shfl_up_sync(0xffffffffu, vr, 8);
        ti = __shfl_up_sync(0xffffffffu, vi, 8);
        if (tgm >= 2) {
            vr = fmaf(l16.x, tr, fmaf(-l16.y, ti, vr));
            vi = fmaf(l16.x, ti, fmaf( l16.y, tr, vi));
        }
        float Cr = __shfl_up_sync(0xffffffffu, vr, 4);
        float Ci = __shfl_up_sync(0xffffffffu, vi, 4);
        if (tgm == 0) { Cr = 0.f; Ci = 0.f; }

        float pwr = lam.x, pwi = lam.y;
        // states column q = w*32 + i*4 + ngl  (channel n lives in column q)
        float2* sp = g_states + (tbase + tg * 8) * N_ST + (w * 32 + i * 4 + ngl);
        #pragma unroll
        for (int j = 0; j < 8; j++) {
            float rr = fmaf(pwr, Cr, fmaf(-pwi, Ci, sr[j]));
            float ri = fmaf(pwr, Ci, fmaf( pwi, Cr, si[j]));
            sp[j * N_ST] = make_float2(rr, ri);
            if (j == 7 && tgm == 3) g_carry[cblk * N_ST + n] = make_float2(rr, ri);
            float npr = fmaf(pwr, lam.x, -pwi * lam.y);
            float npi = fmaf(pwr, lam.y,  pwi * lam.x);
            pwr = npr; pwi = npi;
        }
    }
}

// ---------------- kernel 1b: exclusive prefix over chunk carries ----------------
__global__ void lru_prefix() {
    int b = blockIdx.x;            // 8
    int n = threadIdx.x;           // 256
    float2 lamL = g_lamL[n];
    float2 pre = make_float2(0.f, 0.f);
    const float2* cp = g_carry + b * CHUNKS * N_ST + n;
    float2*       pp = g_pref  + b * CHUNKS * N_ST + n;
    #pragma unroll 1
    for (int cb = 0; cb < CHUNKS; cb += 16) {
        float2 cj[16];
        #pragma unroll
        for (int u = 0; u < 16; u++) cj[u] = cp[(cb + u) * N_ST];
        #pragma unroll
        for (int u = 0; u < 16; u++) {
            pp[(cb + u) * N_ST] = pre;
            pre = cmul(lamL, pre);
            pre.x += cj[u].x; pre.y += cj[u].y;
        }
    }
}

// ---------------- kernel 2: correction + y = Re(states @ C^T) + x @ D^T ----------------
// smem: stT u64[32][130] = 33280B | ct u64[32*16*10] = 40960B  -> 74240B
#define K2_SMEM (32 * 130 * 8 + 32 * 16 * 10 * 8)

__global__ __launch_bounds__(256, 1) void lru_fix_out(const float* __restrict__ x,
                                                      float* __restrict__ y) {
    extern __shared__ char smem[];
    u64* stT = (u64*)smem;                        // [row][sigma(t)], sigma = (t>>3)|((t&7)<<4)
    u64* ct  = (u64*)(smem + 32 * 130 * 8);

    int b   = blockIdx.x >> 5;
    int c2  = blockIdx.x & 31;
    int tid = threadIdx.x;
    int lane = tid & 31, w = tid >> 5;
    int dgl = lane & 3, tgl = lane >> 2;
    int dg  = (w & 3) * 4 + dgl;                  // 0..15
    int tg  = (w >> 2) * 8 + tgl;                 // 0..15
    size_t tbase = (size_t)b * T_LEN + c2 * TT2;
    int row = tid & 31, tseg = tid >> 5;          // phase-A mapping

    u64 acc[64];
    #pragma unroll
    for (int i = 0; i < 64; i++) acc[i] = 0ULL;

    for (int nt = 0; nt < 10; nt++) {
        __syncthreads();
        // ---- load ct tile ----
        {
            const float4* src = (const float4*)(g_CDsw + nt * 5120);
            float4* dst = (float4*)ct;
            #pragma unroll
            for (int i = 0; i < 10; i++) dst[tid + i * 256] = src[tid + i * 256];
        }
        // ---- phase A: build stT tile (32 rows x 128 t) ----
        {
            int q = nt * 32 + row;
            int t0 = tseg * 16;
            if (q < N_ST) {
                int n = qperm(q);
                float2 lam = g_lam[n];
                float2 l2 = cmul(lam, lam), l4 = cmul(l2, l2);
                float2 l8c = cmul(l4, l4), l16 = cmul(l8c, l8c);
                float2 pre = g_pref[(b * CHUNKS + c2 * 4 + (tseg >> 1)) * N_ST + n];
                float2 pw = (tseg & 1) ? cmul(l16, lam) : lam;
                const float2* sp = g_states + (tbase + t0) * N_ST + q;
                #pragma unroll
                for (int i = 0; i < 16; i++) {
                    float2 lv = sp[i * N_ST];
                    float rr = fmaf(pw.x, pre.x, fmaf(-pw.y, pre.y, lv.x));
                    float ri = fmaf(pw.x, pre.y, fmaf( pw.y, pre.x, lv.y));
                    int t = t0 + i;
                    stT[row * 130 + ((t >> 3) | ((t & 7) << 4))] = pk2(rr, ri);
                    float npr = fmaf(pw.x, lam.x, -pw.y * lam.y);
                    float npi = fmaf(pw.x, lam.y,  pw.y * lam.x);
                    pw.x = npr; pw.y = npi;
                }
            } else {
                int kp = q - N_ST;
                const float* xp = x + (tbase + t0) * D_INP + 2 * kp;
                #pragma unroll
                for (int i = 0; i < 16; i++) {
                    int t = t0 + i;
                    stT[row * 130 + ((t >> 3) | ((t & 7) << 4))] =
                        *(const u64*)(xp + (size_t)i * D_INP);
                }
            }
        }
        __syncthreads();
        // ---- phase B: GEMM over this 32-row tile ----
        #pragma unroll 4
        for (int kk = 0; kk < 32; kk++) {
            const ulonglong2* cp2 = (const ulonglong2*)(ct + (kk * 16 + dg) * 10);
            ulonglong2 c01 = cp2[0], c23 = cp2[1], c45 = cp2[2], c67 = cp2[3];
            const u64* sr = stT + kk * 130 + tg;
            u64 sv[8];
            #pragma unroll
            for (int j = 0; j < 8; j++) sv[j] = sr[j * 16];
            u64 cv[8] = {c01.x, c01.y, c23.x, c23.y, c45.x, c45.y, c67.x, c67.y};
            #pragma unroll
            for (int i = 0; i < 8; i++)
                #pragma unroll
                for (int j = 0; j < 8; j++)
                    acc[i * 8 + j] = fma2(sv[j], cv[i], acc[i * 8 + j]);
        }
    }

    // ---- epilogue: Re() = lo - hi (D-term folded via sign trick) ----
    float* yp = y + (tbase + tg * 8) * D_OUTP + dg * 8;
    #pragma unroll
    for (int j = 0; j < 8; j++) {
        float r[8];
        #pragma unroll
        for (int i = 0; i < 8; i++) {
            float a, bb; upk2(acc[i * 8 + j], a, bb);
            r[i] = a - bb;
        }
        *(float4*)(yp + (size_t)j * D_OUTP)     = make_float4(r[0], r[1], r[2], r[3]);
        *(float4*)(yp + (size_t)j * D_OUTP + 4) = make_float4(r[4], r[5], r[6], r[7]);
    }
}

// ---------------- launch ----------------
extern "C" void kernel_launch(void* const* d_in, const int* in_sizes, int n_in,
                              void* d_out, int out_size) {
    (void)in_sizes; (void)n_in; (void)out_size;
    const float* x         = (const float*)d_in[0];
    const float* nu_log    = (const float*)d_in[1];
    const float* theta_log = (const float*)d_in[2];
    const float* gamma_log = (const float*)d_in[3];
    const float* B_re      = (const float*)d_in[4];
    const float* B_im      = (const float*)d_in[5];
    const float* C_re      = (const float*)d_in[6];
    const float* C_im      = (const float*)d_in[7];
    const float* Dm        = (const float*)d_in[8];
    float* y = (float*)d_out;

    cudaFuncSetAttribute(lru_bu_scan, cudaFuncAttributeMaxDynamicSharedMemorySize, K1_SMEM);
    cudaFuncSetAttribute(lru_fix_out, cudaFuncAttributeMaxDynamicSharedMemorySize, K2_SMEM);

    lru_prep<<<200, 256>>>(nu_log, theta_log, gamma_log, B_re, B_im, C_re, C_im, Dm);
    lru_bu_scan<<<NBLK1, 256, K1_SMEM>>>(x);
    lru_prefix<<<B_SZ, N_ST>>>();
    lru_fix_out<<<NBLK2, 256, K2_SMEM>>>(x, y);
}